// round 10
// baseline (speedup 1.0000x reference)
#include <cuda_runtime.h>

#define NN 4096
#define TT 3
#define DD 20
#define EE 131072      // 2^17
#define ATT_DIM 128
#define HEADS 2
#define LAYERS 2
#define WPR 128        // 32-bit words per bitmap row (4096/32)
#define NEG 0.2f
#define MAXDEG 384     // mean degree ~191; MAXDEG/2 = 6*32 u32 pairs
#define L2E 1.4426950408889634f

#define EPT 4                                  // edges per scatter thread
#define SCAT_BLKS (TT * EE / (256 * EPT))      // 384
#define SCORE_BLKS 512                         // 4096 rows / 8 warps
#define PREP_BLKS (SCAT_BLKS + SCORE_BLKS + 1)

#define PASS_BLKS 144                          // single wave on 144-148 SMs
#define ROWS_PB   29                           // 144*29 = 4176 >= 4096
#define PASS_THREADS (ROWS_PB * 32)            // 928

// ---- device scratch (static, allocation-free) ----
// 3 separate bitmaps (6MB). Start zeroed (.bss); k_pass0 re-zeroes after
// reading -> invariant holds across graph replays.
__device__ __align__(16) unsigned g_bm[TT][NN * WPR];          // 6MB
__device__ __align__(16) unsigned short g_ent[NN * MAXDEG];    // j | (m<<12)
__device__ int    g_cnt[NN];                                   // even (padded)
__device__ __align__(16) float g_s0[NN];
__device__ __align__(16) float g_s1[NN];
__device__ float4 g_tab[LAYERS][8];   // per-mask: (lut_h0', lut_h1', M, _)
__device__ float  g_ab[LAYERS][4];    // a0', b0', a1', b1' (log2e folded)

__device__ __forceinline__ float ex2f(float x) {
    float r;
    asm("ex2.approx.ftz.f32 %0, %1;" : "=f"(r) : "f"(x));
    return r;
}

__device__ __forceinline__ void red_or(unsigned* p, unsigned v) {
    asm volatile("red.global.or.b32 [%0], %1;" :: "l"(p), "r"(v) : "memory");
}

// ----------------------- fused: edge scatter + initial scores + constants
__global__ void __launch_bounds__(256) k_prep(const int* __restrict__ el,
                                              const float* __restrict__ inputs,
                                              const float* __restrict__ lw,
                                              const float* __restrict__ lb,
                                              const float* __restrict__ edge_emb,
                                              const float* __restrict__ att_w) {
    int bid = blockIdx.x, tid = threadIdx.x;

    if (bid < SCAT_BLKS) {
        // ---- edge scatter: 4 edges/thread, 2x LDG.128 then 8 fire-and-forget REDs
        int i0 = (bid * 256 + tid) * EPT;      // multiple of 4; same t for all 4
        int t  = i0 >> 17;                     // EE = 2^17
        int e  = i0 & (EE - 1);
        int4 sv = *reinterpret_cast<const int4*>(&el[(t * 2 + 0) * EE + e]);
        int4 gv = *reinterpret_cast<const int4*>(&el[(t * 2 + 1) * EE + e]);
        unsigned* bm = &g_bm[t][0];
        red_or(&bm[sv.x * WPR + (gv.x >> 5)], 1u << (gv.x & 31));
        red_or(&bm[gv.x * WPR + (sv.x >> 5)], 1u << (sv.x & 31));
        red_or(&bm[sv.y * WPR + (gv.y >> 5)], 1u << (gv.y & 31));
        red_or(&bm[gv.y * WPR + (sv.y >> 5)], 1u << (sv.y & 31));
        red_or(&bm[sv.z * WPR + (gv.z >> 5)], 1u << (gv.z & 31));
        red_or(&bm[gv.z * WPR + (sv.z >> 5)], 1u << (sv.z & 31));
        red_or(&bm[sv.w * WPR + (gv.w >> 5)], 1u << (gv.w & 31));
        red_or(&bm[gv.w * WPR + (sv.w >> 5)], 1u << (sv.w & 31));
    } else if (bid < SCAT_BLKS + SCORE_BLKS) {
        // ---- initial linear scores: one row per warp, 8 warps
        int warp = tid >> 5, lane = tid & 31;
        int row  = (bid - SCAT_BLKS) * 8 + warp;
        float4 v = reinterpret_cast<const float4*>(inputs + row * ATT_DIM)[lane];
        float4 w = reinterpret_cast<const float4*>(lw)[lane];
        float acc = v.x * w.x + v.y * w.y + v.z * w.z + v.w * w.w;
        #pragma unroll
        for (int o = 16; o; o >>= 1) acc += __shfl_xor_sync(0xFFFFFFFFu, acc, o);
        if (lane == 0) g_s0[row] = acc + lb[0];
    } else {
        // ---- per-(layer,head) constants
        float* tabf = reinterpret_cast<float*>(&g_tab[0][0]);
        if (tid < LAYERS * HEADS) {
            int l = tid >> 1, h = tid & 1;
            const float* w = att_w + (l * HEADS + h) * (DD + 2);
            float et[TT];
            #pragma unroll
            for (int t = 0; t < TT; t++) {
                float acc = 0.0f;
                #pragma unroll
                for (int d = 0; d < DD; d++) acc += edge_emb[t * DD + d] * w[1 + d];
                et[t] = acc * L2E;
            }
            g_ab[l][h * 2 + 0] = w[0] * L2E;
            g_ab[l][h * 2 + 1] = w[DD + 1] * L2E;
            #pragma unroll
            for (int m = 0; m < 8; m++) {
                float B = 0.0f;
                #pragma unroll
                for (int t = 0; t < TT; t++) if ((m >> t) & 1) B += et[t];
                tabf[(l * 8 + m) * 4 + h] = B;
            }
        } else if (tid < LAYERS * HEADS + 2) {
            int l = tid - LAYERS * HEADS;
            #pragma unroll
            for (int m = 0; m < 8; m++)
                tabf[(l * 8 + m) * 4 + 2] = (float)__popc((unsigned)m);
        }
    }
}

// ---------------- fused: CSR build (own 29 rows) + attention layer 0
// 144 blocks x 928 threads; warp w owns row blk*29+w (guarded); lane owns
// 4 bitmap words per type.
__global__ void __launch_bounds__(PASS_THREADS) k_pass0() {
    __shared__ float  ss[NN];                                     // 16KB
    __shared__ __align__(16) unsigned short se[ROWS_PB][MAXDEG];  // ~22KB
    __shared__ float4 tab[8];
    __shared__ float  ab[4];
    __shared__ float  red[ROWS_PB];
    __shared__ float  shS;

    int tid = threadIdx.x, warp = tid >> 5, lane = tid & 31;
    int row = blockIdx.x * ROWS_PB + warp;
    bool live = (row < NN);

    // ---- A: read this row's bitmap words (uint4 per type), zero-restore
    uint4 a0, a1, a2;
    uint4 *b0p = 0, *b1p = 0, *b2p = 0;
    if (live) {
        b0p = reinterpret_cast<uint4*>(&g_bm[0][0]) + row * 32 + lane;
        b1p = reinterpret_cast<uint4*>(&g_bm[1][0]) + row * 32 + lane;
        b2p = reinterpret_cast<uint4*>(&g_bm[2][0]) + row * 32 + lane;
        a0 = *b0p; a1 = *b1p; a2 = *b2p;
    } else {
        a0 = a1 = a2 = make_uint4(0u, 0u, 0u, 0u);
    }

    // ---- B: stage scores + S0 partials (overlaps bitmap scoreboard waits)
    float part = 0.0f;
    for (int i = tid; i < NN / 4; i += PASS_THREADS) {
        float4 sv = __ldcg(reinterpret_cast<const float4*>(g_s0) + i);
        reinterpret_cast<float4*>(ss)[i] = sv;
        part += (sv.x + sv.y) + (sv.z + sv.w);
    }
    #pragma unroll
    for (int o = 16; o; o >>= 1) part += __shfl_xor_sync(0xFFFFFFFFu, part, o);
    if (lane == 0) red[warp] = part;
    if (tid < 8)       tab[tid]    = g_tab[0][tid];
    else if (tid < 12) ab[tid - 8] = g_ab[0][tid - 8];

    if (live) {
        uint4 z = make_uint4(0u, 0u, 0u, 0u);
        *b0p = z; *b1p = z; *b2p = z;             // restore zero invariant
    }

    // ---- C: per-lane counts + warp scan
    unsigned u0 = a0.x | a1.x | a2.x;
    unsigned u1 = a0.y | a1.y | a2.y;
    unsigned u2 = a0.z | a1.z | a2.z;
    unsigned u3 = a0.w | a1.w | a2.w;
    int cnt = __popc(u0) + __popc(u1) + __popc(u2) + __popc(u3);

    int inc = cnt;
    #pragma unroll
    for (int o = 1; o < 32; o <<= 1) {
        int n = __shfl_up_sync(0xFFFFFFFFu, inc, o);
        if (lane >= o) inc += n;
    }
    int base = inc - cnt;
    int tot  = __shfl_sync(0xFFFFFFFFu, inc, 31);

    // ---- D: extract into this warp's smem CSR row
    unsigned short* sw = &se[warp][0];
    #pragma unroll
    for (int c = 0; c < 4; c++) {
        unsigned u  = (c == 0) ? u0   : (c == 1) ? u1   : (c == 2) ? u2   : u3;
        unsigned w0 = (c == 0) ? a0.x : (c == 1) ? a0.y : (c == 2) ? a0.z : a0.w;
        unsigned w1 = (c == 0) ? a1.x : (c == 1) ? a1.y : (c == 2) ? a1.z : a1.w;
        unsigned w2 = (c == 0) ? a2.x : (c == 1) ? a2.y : (c == 2) ? a2.z : a2.w;
        int col = (lane * 4 + c) * 32;
        while (u) {
            int b = __ffs(u) - 1;
            u &= u - 1;
            int m = ((w0 >> b) & 1) | (((w1 >> b) & 1) << 1) | (((w2 >> b) & 1) << 2);
            sw[base++] = (unsigned short)((col + b) | (m << 12));
        }
    }
    if (lane == 31 && (tot & 1)) sw[tot] = 0;     // pad entry (exact no-op)
    int cpad = (tot + 1) & ~1;
    if (live && lane == 0) g_cnt[row] = cpad;
    __syncwarp();

    // ---- E: stream entries to gmem for layer 1 (48 uint4, coalesced)
    if (live) {
        uint4* go = reinterpret_cast<uint4*>(&g_ent[row * MAXDEG]);
        const uint4* so = reinterpret_cast<const uint4*>(sw);
        go[lane] = so[lane];
        if (lane < 16) go[lane + 32] = so[lane + 32];
    }

    __syncthreads();                                 // ss + red ready
    if (tid < 32) {
        float v = (tid < ROWS_PB) ? red[tid] : 0.0f;
        #pragma unroll
        for (int o = 16; o; o >>= 1) v += __shfl_xor_sync(0xFFFFFFFFu, v, o);
        if (tid == 0) shS = v;
    }
    __syncthreads();

    // ---- F: layer-0 attention, entries from smem
    float S  = shS;
    float si = ss[live ? row : 0];
    float a0f = ab[0], b0f = ab[1], a1f = ab[2], b1f = ab[3];
    float c0 = a0f * si, c1 = a1f * si;

    const unsigned* ep32 = reinterpret_cast<const unsigned*>(sw);
    int nit = cpad >> 1;
    float e0 = 0.0f, n0 = 0.0f, e1 = 0.0f, n1 = 0.0f, sjs = 0.0f;

    for (int k = lane; k < nit; k += 32) {
        unsigned pr = ep32[k];
        #pragma unroll
        for (int half = 0; half < 2; half++) {
            int e = (half == 0) ? (pr & 0xFFFFu) : (pr >> 16);
            int j = e & 0xFFF;
            int m = e >> 12;
            float4 t4 = tab[m];           // (lut0', lut1', M, _)
            float sj = ss[j];
            float M  = t4.z;

            float x0 = fmaf(M, fmaf(b0f, sj, c0), t4.x);
            x0 = fmaxf(x0, NEG * x0);     // lrelu commutes with log2e scale
            float v0 = ex2f(x0);
            e0 += v0; n0 = fmaf(v0, sj, n0);

            float x1 = fmaf(M, fmaf(b1f, sj, c1), t4.y);
            x1 = fmaxf(x1, NEG * x1);
            float v1 = ex2f(x1);
            e1 += v1; n1 = fmaf(v1, sj, n1);

            sjs += sj;
        }
    }

    #pragma unroll
    for (int o = 16; o; o >>= 1) {
        e0  += __shfl_xor_sync(0xFFFFFFFFu, e0,  o);
        n0  += __shfl_xor_sync(0xFFFFFFFFu, n0,  o);
        e1  += __shfl_xor_sync(0xFFFFFFFFu, e1,  o);
        n1  += __shfl_xor_sync(0xFFFFFFFFu, n1,  o);
        sjs += __shfl_xor_sync(0xFFFFFFFFu, sjs, o);
    }
    if (live && lane == 0) {
        float fc = (float)cpad;
        float r0 = (S + n0 - sjs) / ((float)NN + e0 - fc);
        float r1 = (S + n1 - sjs) / ((float)NN + e1 - fc);
        g_s1[row] = 0.5f * (r0 + r1);
    }
}

// ------------------------------------- layer-1 attention (entries L2-warm)
__global__ void __launch_bounds__(PASS_THREADS) k_pass1(float* __restrict__ out) {
    __shared__ float  ss[NN];
    __shared__ float4 tab[8];
    __shared__ float  ab[4];
    __shared__ float  red[ROWS_PB];
    __shared__ float  shS;

    int tid = threadIdx.x, warp = tid >> 5, lane = tid & 31;
    int row = blockIdx.x * ROWS_PB + warp;
    bool live = (row < NN);

    int cnt = live ? g_cnt[row] : 0;
    const unsigned* __restrict__ ep32 =
        reinterpret_cast<const unsigned*>(&g_ent[(live ? row : 0) * MAXDEG]);
    unsigned pr[6];
    #pragma unroll
    for (int q = 0; q < 6; q++) pr[q] = ep32[lane + q * 32];   // MLP=6

    float part = 0.0f;
    for (int i = tid; i < NN / 4; i += PASS_THREADS) {
        float4 sv = __ldcg(reinterpret_cast<const float4*>(g_s1) + i);
        reinterpret_cast<float4*>(ss)[i] = sv;
        part += (sv.x + sv.y) + (sv.z + sv.w);
    }
    #pragma unroll
    for (int o = 16; o; o >>= 1) part += __shfl_xor_sync(0xFFFFFFFFu, part, o);
    if (lane == 0) red[warp] = part;
    if (tid < 8)       tab[tid]    = g_tab[1][tid];
    else if (tid < 12) ab[tid - 8] = g_ab[1][tid - 8];
    __syncthreads();

    if (tid < 32) {
        float v = (tid < ROWS_PB) ? red[tid] : 0.0f;
        #pragma unroll
        for (int o = 16; o; o >>= 1) v += __shfl_xor_sync(0xFFFFFFFFu, v, o);
        if (tid == 0) shS = v;
    }
    __syncthreads();

    float S  = shS;
    float si = ss[live ? row : 0];
    float a0f = ab[0], b0f = ab[1], a1f = ab[2], b1f = ab[3];
    float c0 = a0f * si, c1 = a1f * si;

    int nit = cnt >> 1;
    float e0 = 0.0f, n0 = 0.0f, e1 = 0.0f, n1 = 0.0f, sjs = 0.0f;

    #pragma unroll
    for (int q = 0; q < 6; q++) {
        if (lane + q * 32 < nit) {
            unsigned prq = pr[q];
            #pragma unroll
            for (int half = 0; half < 2; half++) {
                int e = (half == 0) ? (prq & 0xFFFFu) : (prq >> 16);
                int j = e & 0xFFF;
                int m = e >> 12;
                float4 t4 = tab[m];
                float sj = ss[j];
                float M  = t4.z;

                float x0 = fmaf(M, fmaf(b0f, sj, c0), t4.x);
                x0 = fmaxf(x0, NEG * x0);
                float v0 = ex2f(x0);
                e0 += v0; n0 = fmaf(v0, sj, n0);

                float x1 = fmaf(M, fmaf(b1f, sj, c1), t4.y);
                x1 = fmaxf(x1, NEG * x1);
                float v1 = ex2f(x1);
                e1 += v1; n1 = fmaf(v1, sj, n1);

                sjs += sj;
            }
        }
    }

    #pragma unroll
    for (int o = 16; o; o >>= 1) {
        e0  += __shfl_xor_sync(0xFFFFFFFFu, e0,  o);
        n0  += __shfl_xor_sync(0xFFFFFFFFu, n0,  o);
        e1  += __shfl_xor_sync(0xFFFFFFFFu, e1,  o);
        n1  += __shfl_xor_sync(0xFFFFFFFFu, n1,  o);
        sjs += __shfl_xor_sync(0xFFFFFFFFu, sjs, o);
    }
    if (live && lane == 0) {
        float fc = (float)cnt;
        float r0 = (S + n0 - sjs) / ((float)NN + e0 - fc);
        float r1 = (S + n1 - sjs) / ((float)NN + e1 - fc);
        out[row] = 0.5f * (r0 + r1);
    }
}

// ---------------------------------------------------------------- launch
extern "C" void kernel_launch(void* const* d_in, const int* in_sizes, int n_in,
                              void* d_out, int out_size) {
    const float* inputs     = (const float*)d_in[0];
    const float* lin_w      = (const float*)d_in[1];
    const float* lin_b      = (const float*)d_in[2];
    const float* edge_emb   = (const float*)d_in[3];
    const float* att_w      = (const float*)d_in[4];
    const int*   edge_lists = (const int*)  d_in[5];
    float* out = (float*)d_out;

    k_prep <<<PREP_BLKS, 256>>>(edge_lists, inputs, lin_w, lin_b, edge_emb, att_w);
    k_pass0<<<PASS_BLKS, PASS_THREADS>>>();
    k_pass1<<<PASS_BLKS, PASS_THREADS>>>(out);
}

// round 11
// speedup vs baseline: 1.0983x; 1.0983x over previous
#include <cuda_runtime.h>

#define NN 4096
#define TT 3
#define DD 20
#define EE 131072      // 2^17
#define ATT_DIM 128
#define HEADS 2
#define LAYERS 2
#define WPR 128        // 32-bit words per bitmap row (4096/32)
#define NEG 0.2f
#define MAXDEG 384     // mean degree ~191; MAXDEG/2 = 6*32 u32 pairs
#define L2E 1.4426950408889634f

#define SCAT_BLKS (TT * EE * 2 / 256)          // 3072: one directed half-edge/thread
#define SCORE_BLKS 512                         // 4096 rows / 8 warps
#define PREP_BLKS (SCAT_BLKS + SCORE_BLKS + 1)
#define PASS_BLKS 128                          // 32 rows/block, single wave

// ---- device scratch (static, allocation-free) ----
// 3 separate bitmaps (6MB). Start zeroed (.bss); k_pass0 re-zeroes after
// reading -> invariant holds across graph replays.
__device__ __align__(16) unsigned g_bm[TT][NN * WPR];          // 6MB
__device__ __align__(16) unsigned short g_ent[NN * MAXDEG];    // j | (m<<12)
__device__ int    g_cnt[NN];                                   // even (padded)
__device__ __align__(16) float g_s0[NN];
__device__ __align__(16) float g_s1[NN];
__device__ float4 g_tab[LAYERS][8];   // per-mask: (lut_h0', lut_h1', M, _)
__device__ float  g_ab[LAYERS][4];    // a0', b0', a1', b1' (log2e folded)

__device__ __forceinline__ float ex2f(float x) {
    float r;
    asm("ex2.approx.ftz.f32 %0, %1;" : "=f"(r) : "f"(x));
    return r;
}

__device__ __forceinline__ void red_or(unsigned* p, unsigned v) {
    asm volatile("red.global.or.b32 [%0], %1;" :: "l"(p), "r"(v) : "memory");
}

// ----------------------- fused: edge scatter + initial scores + constants
__global__ void __launch_bounds__(256) k_prep(const int* __restrict__ el,
                                              const float* __restrict__ inputs,
                                              const float* __restrict__ lw,
                                              const float* __restrict__ lb,
                                              const float* __restrict__ edge_emb,
                                              const float* __restrict__ att_w) {
    int bid = blockIdx.x, tid = threadIdx.x;

    if (bid < SCAT_BLKS) {
        // ---- edge scatter: one DIRECTED half-edge per thread (max concurrency)
        int i   = bid * 256 + tid;         // i < 2*TT*EE
        int dir = i & 1;
        int eid = i >> 1;                  // eid < TT*EE
        int t   = eid >> 17;               // EE = 2^17
        int e   = eid & (EE - 1);
        int s = el[(t * 2 + 0) * EE + e];
        int g = el[(t * 2 + 1) * EE + e];
        int from = dir ? g : s;
        int to   = dir ? s : g;
        red_or(&g_bm[t][from * WPR + (to >> 5)], 1u << (to & 31));
    } else if (bid < SCAT_BLKS + SCORE_BLKS) {
        // ---- initial linear scores: one row per warp, 8 warps
        int warp = tid >> 5, lane = tid & 31;
        int row  = (bid - SCAT_BLKS) * 8 + warp;
        float4 v = reinterpret_cast<const float4*>(inputs + row * ATT_DIM)[lane];
        float4 w = reinterpret_cast<const float4*>(lw)[lane];
        float acc = v.x * w.x + v.y * w.y + v.z * w.z + v.w * w.w;
        #pragma unroll
        for (int o = 16; o; o >>= 1) acc += __shfl_xor_sync(0xFFFFFFFFu, acc, o);
        if (lane == 0) g_s0[row] = acc + lb[0];
    } else {
        // ---- per-(layer,head) constants
        float* tabf = reinterpret_cast<float*>(&g_tab[0][0]);
        if (tid < LAYERS * HEADS) {
            int l = tid >> 1, h = tid & 1;
            const float* w = att_w + (l * HEADS + h) * (DD + 2);
            float et[TT];
            #pragma unroll
            for (int t = 0; t < TT; t++) {
                float acc = 0.0f;
                #pragma unroll
                for (int d = 0; d < DD; d++) acc += edge_emb[t * DD + d] * w[1 + d];
                et[t] = acc * L2E;
            }
            g_ab[l][h * 2 + 0] = w[0] * L2E;
            g_ab[l][h * 2 + 1] = w[DD + 1] * L2E;
            #pragma unroll
            for (int m = 0; m < 8; m++) {
                float B = 0.0f;
                #pragma unroll
                for (int t = 0; t < TT; t++) if ((m >> t) & 1) B += et[t];
                tabf[(l * 8 + m) * 4 + h] = B;
            }
        } else if (tid < LAYERS * HEADS + 2) {
            int l = tid - LAYERS * HEADS;
            #pragma unroll
            for (int m = 0; m < 8; m++)
                tabf[(l * 8 + m) * 4 + 2] = (float)__popc((unsigned)m);
        }
    }
}

// ---------------- fused: CSR build (own 32 rows) + attention layer 0
// 128 blocks x 1024 threads; warp w owns row blk*32+w; lane owns 4 words/type.
__global__ void __launch_bounds__(1024) k_pass0() {
    __shared__ float  ss[NN];                                // 16KB scores
    __shared__ __align__(16) unsigned short se[32][MAXDEG];  // 24KB CSR rows
    __shared__ float4 tab[8];
    __shared__ float  ab[4];
    __shared__ float  red[32];
    __shared__ float  shS;

    int tid = threadIdx.x, warp = tid >> 5, lane = tid & 31;
    int row = blockIdx.x * 32 + warp;

    // ---- A: read this row's bitmap words (uint4 per type), zero-restore
    uint4* b0p = reinterpret_cast<uint4*>(&g_bm[0][0]) + row * 32 + lane;
    uint4* b1p = reinterpret_cast<uint4*>(&g_bm[1][0]) + row * 32 + lane;
    uint4* b2p = reinterpret_cast<uint4*>(&g_bm[2][0]) + row * 32 + lane;
    uint4 a0 = *b0p, a1 = *b1p, a2 = *b2p;

    // ---- B: stage scores + S0 partials (overlaps bitmap scoreboard waits)
    float4 sv = __ldcg(reinterpret_cast<const float4*>(g_s0) + tid);
    reinterpret_cast<float4*>(ss)[tid] = sv;
    float part = (sv.x + sv.y) + (sv.z + sv.w);
    #pragma unroll
    for (int o = 16; o; o >>= 1) part += __shfl_xor_sync(0xFFFFFFFFu, part, o);
    if (lane == 0) red[warp] = part;
    if (tid < 8)       tab[tid]    = g_tab[0][tid];
    else if (tid < 12) ab[tid - 8] = g_ab[0][tid - 8];

    uint4 z = make_uint4(0u, 0u, 0u, 0u);
    *b0p = z; *b1p = z; *b2p = z;                 // restore zero invariant

    // ---- C: per-lane counts + warp scan
    unsigned u0 = a0.x | a1.x | a2.x;
    unsigned u1 = a0.y | a1.y | a2.y;
    unsigned u2 = a0.z | a1.z | a2.z;
    unsigned u3 = a0.w | a1.w | a2.w;
    int cnt = __popc(u0) + __popc(u1) + __popc(u2) + __popc(u3);

    int inc = cnt;
    #pragma unroll
    for (int o = 1; o < 32; o <<= 1) {
        int n = __shfl_up_sync(0xFFFFFFFFu, inc, o);
        if (lane >= o) inc += n;
    }
    int base = inc - cnt;
    int tot  = __shfl_sync(0xFFFFFFFFu, inc, 31);

    // ---- D: extract into this warp's smem CSR row
    unsigned short* sw = &se[warp][0];
    #pragma unroll
    for (int c = 0; c < 4; c++) {
        unsigned u  = (c == 0) ? u0   : (c == 1) ? u1   : (c == 2) ? u2   : u3;
        unsigned w0 = (c == 0) ? a0.x : (c == 1) ? a0.y : (c == 2) ? a0.z : a0.w;
        unsigned w1 = (c == 0) ? a1.x : (c == 1) ? a1.y : (c == 2) ? a1.z : a1.w;
        unsigned w2 = (c == 0) ? a2.x : (c == 1) ? a2.y : (c == 2) ? a2.z : a2.w;
        int col = (lane * 4 + c) * 32;
        while (u) {
            int b = __ffs(u) - 1;
            u &= u - 1;
            int m = ((w0 >> b) & 1) | (((w1 >> b) & 1) << 1) | (((w2 >> b) & 1) << 2);
            sw[base++] = (unsigned short)((col + b) | (m << 12));
        }
    }
    if (lane == 31 && (tot & 1)) sw[tot] = 0;     // pad entry (exact no-op)
    int cpad = (tot + 1) & ~1;
    if (lane == 0) g_cnt[row] = cpad;
    __syncwarp();

    // ---- E: stream entries to gmem for layer 1 (48 uint4, coalesced)
    {
        uint4* go = reinterpret_cast<uint4*>(&g_ent[row * MAXDEG]);
        const uint4* so = reinterpret_cast<const uint4*>(sw);
        go[lane] = so[lane];
        if (lane < 16) go[lane + 32] = so[lane + 32];
    }

    __syncthreads();                                 // ss + red ready
    if (tid < 32) {
        float v = red[tid];
        #pragma unroll
        for (int o = 16; o; o >>= 1) v += __shfl_xor_sync(0xFFFFFFFFu, v, o);
        if (tid == 0) shS = v;
    }
    __syncthreads();

    // ---- F: layer-0 attention, entries from smem
    float S  = shS;
    float si = ss[row];
    float a0f = ab[0], b0f = ab[1], a1f = ab[2], b1f = ab[3];
    float c0 = a0f * si, c1 = a1f * si;

    const unsigned* ep32 = reinterpret_cast<const unsigned*>(sw);
    int nit = cpad >> 1;
    float e0 = 0.0f, n0 = 0.0f, e1 = 0.0f, n1 = 0.0f, sjs = 0.0f;

    for (int k = lane; k < nit; k += 32) {
        unsigned pr = ep32[k];
        #pragma unroll
        for (int half = 0; half < 2; half++) {
            int e = (half == 0) ? (pr & 0xFFFFu) : (pr >> 16);
            int j = e & 0xFFF;
            int m = e >> 12;
            float4 t4 = tab[m];           // (lut0', lut1', M, _)
            float sj = ss[j];
            float M  = t4.z;

            float x0 = fmaf(M, fmaf(b0f, sj, c0), t4.x);
            x0 = fmaxf(x0, NEG * x0);     // lrelu commutes with log2e scale
            float v0 = ex2f(x0);
            e0 += v0; n0 = fmaf(v0, sj, n0);

            float x1 = fmaf(M, fmaf(b1f, sj, c1), t4.y);
            x1 = fmaxf(x1, NEG * x1);
            float v1 = ex2f(x1);
            e1 += v1; n1 = fmaf(v1, sj, n1);

            sjs += sj;
        }
    }

    #pragma unroll
    for (int o = 16; o; o >>= 1) {
        e0  += __shfl_xor_sync(0xFFFFFFFFu, e0,  o);
        n0  += __shfl_xor_sync(0xFFFFFFFFu, n0,  o);
        e1  += __shfl_xor_sync(0xFFFFFFFFu, e1,  o);
        n1  += __shfl_xor_sync(0xFFFFFFFFu, n1,  o);
        sjs += __shfl_xor_sync(0xFFFFFFFFu, sjs, o);
    }
    if (lane == 0) {
        float fc = (float)cpad;
        float r0 = (S + n0 - sjs) / ((float)NN + e0 - fc);
        float r1 = (S + n1 - sjs) / ((float)NN + e1 - fc);
        g_s1[row] = 0.5f * (r0 + r1);
    }
}

// ------------------------------------- layer-1 attention (entries L2-warm)
__global__ void __launch_bounds__(1024) k_pass1(float* __restrict__ out) {
    __shared__ float  ss[NN];
    __shared__ float4 tab[8];
    __shared__ float  ab[4];
    __shared__ float  red[32];
    __shared__ float  shS;

    int tid = threadIdx.x, warp = tid >> 5, lane = tid & 31;
    int row = blockIdx.x * 32 + warp;

    int cnt = g_cnt[row];
    const unsigned* __restrict__ ep32 =
        reinterpret_cast<const unsigned*>(&g_ent[row * MAXDEG]);
    unsigned pr[6];
    #pragma unroll
    for (int q = 0; q < 6; q++) pr[q] = ep32[lane + q * 32];   // MLP=6

    float4 sv = __ldcg(reinterpret_cast<const float4*>(g_s1) + tid);
    reinterpret_cast<float4*>(ss)[tid] = sv;
    float part = (sv.x + sv.y) + (sv.z + sv.w);
    #pragma unroll
    for (int o = 16; o; o >>= 1) part += __shfl_xor_sync(0xFFFFFFFFu, part, o);
    if (lane == 0) red[warp] = part;
    if (tid < 8)       tab[tid]    = g_tab[1][tid];
    else if (tid < 12) ab[tid - 8] = g_ab[1][tid - 8];
    __syncthreads();

    if (tid < 32) {
        float v = red[tid];
        #pragma unroll
        for (int o = 16; o; o >>= 1) v += __shfl_xor_sync(0xFFFFFFFFu, v, o);
        if (tid == 0) shS = v;
    }
    __syncthreads();

    float S  = shS;
    float si = ss[row];
    float a0f = ab[0], b0f = ab[1], a1f = ab[2], b1f = ab[3];
    float c0 = a0f * si, c1 = a1f * si;

    int nit = cnt >> 1;
    float e0 = 0.0f, n0 = 0.0f, e1 = 0.0f, n1 = 0.0f, sjs = 0.0f;

    #pragma unroll
    for (int q = 0; q < 6; q++) {
        if (lane + q * 32 < nit) {
            unsigned prq = pr[q];
            #pragma unroll
            for (int half = 0; half < 2; half++) {
                int e = (half == 0) ? (prq & 0xFFFFu) : (prq >> 16);
                int j = e & 0xFFF;
                int m = e >> 12;
                float4 t4 = tab[m];
                float sj = ss[j];
                float M  = t4.z;

                float x0 = fmaf(M, fmaf(b0f, sj, c0), t4.x);
                x0 = fmaxf(x0, NEG * x0);
                float v0 = ex2f(x0);
                e0 += v0; n0 = fmaf(v0, sj, n0);

                float x1 = fmaf(M, fmaf(b1f, sj, c1), t4.y);
                x1 = fmaxf(x1, NEG * x1);
                float v1 = ex2f(x1);
                e1 += v1; n1 = fmaf(v1, sj, n1);

                sjs += sj;
            }
        }
    }

    #pragma unroll
    for (int o = 16; o; o >>= 1) {
        e0  += __shfl_xor_sync(0xFFFFFFFFu, e0,  o);
        n0  += __shfl_xor_sync(0xFFFFFFFFu, n0,  o);
        e1  += __shfl_xor_sync(0xFFFFFFFFu, e1,  o);
        n1  += __shfl_xor_sync(0xFFFFFFFFu, n1,  o);
        sjs += __shfl_xor_sync(0xFFFFFFFFu, sjs, o);
    }
    if (lane == 0) {
        float fc = (float)cnt;
        float r0 = (S + n0 - sjs) / ((float)NN + e0 - fc);
        float r1 = (S + n1 - sjs) / ((float)NN + e1 - fc);
        out[row] = 0.5f * (r0 + r1);
    }
}

// ---------------------------------------------------------------- launch
extern "C" void kernel_launch(void* const* d_in, const int* in_sizes, int n_in,
                              void* d_out, int out_size) {
    const float* inputs     = (const float*)d_in[0];
    const float* lin_w      = (const float*)d_in[1];
    const float* lin_b      = (const float*)d_in[2];
    const float* edge_emb   = (const float*)d_in[3];
    const float* att_w      = (const float*)d_in[4];
    const int*   edge_lists = (const int*)  d_in[5];
    float* out = (float*)d_out;

    k_prep <<<PREP_BLKS, 256>>>(edge_lists, inputs, lin_w, lin_b, edge_emb, att_w);
    k_pass0<<<PASS_BLKS, 1024>>>();
    k_pass1<<<PASS_BLKS, 1024>>>(out);
}